// round 4
// baseline (speedup 1.0000x reference)
#include <cuda_runtime.h>
#include <math.h>

#define Bn 2
#define Cn 21
#define Hn 512
#define Wn 512
#define HL 128
#define WL 128
#define Kn 11
#define SPANn 5
#define KKn 121

// padded pooled-pred buffer: [b][c][144][144], origin (5,8)
#define PP 144
#define XOFF 5
#define YOFF 8
#define PLANE (PP*PP)

// swizzled gk shared row: pix -> (pix>>3)*12 + (pix&7), row stride 384 words
#define GKROW 384

__device__ float g_lg   [Bn*Cn*Hn*Wn];          // log_softmax(unary)
__device__ float g_ppad [Bn*Cn*PLANE];          // pooled pred, zero-padded halo
__device__ float g_msg  [Bn*Cn*HL*WL];          // low-res message
__device__ float g_cf   [Bn*3*HL*WL];           // pooled color feats
__device__ float g_gk   [Bn*8*8*KKn*256];       // gauss kernel, tiled [b][tx][ty][ij][16x16 pix]

__constant__ float c_wtab[4] = {0.375f, 0.125f, 0.875f, 0.625f};

// ---------------------------------------------------------------------------
// 0) zero the padded pooled buffer
__global__ void k_zero() {
    int idx = blockIdx.x * 256 + threadIdx.x;
    if (idx < Bn*Cn*PLANE/4) ((float4*)g_ppad)[idx] = make_float4(0.f,0.f,0.f,0.f);
}

// ---------------------------------------------------------------------------
// 1) pooled color features: avg_pool(img * schan, 4)
__global__ void k_pool_img(const float* __restrict__ img, const float* __restrict__ schan) {
    int idx = blockIdx.x * 256 + threadIdx.x;
    if (idx >= Bn*3*HL*WL) return;
    int y = idx & (WL-1);
    int x = (idx >> 7) & (HL-1);
    int c = (idx >> 14) % 3;
    int b = idx / (3*HL*WL);
    const float* src = img + ((b*3 + c)*Hn + x*4)*Wn + y*4;
    float s = 0.f;
    #pragma unroll
    for (int i = 0; i < 4; i++)
        #pragma unroll
        for (int j = 0; j < 4; j++) s += src[i*Wn + j];
    g_cf[idx] = s * (schan[0] * 0.0625f);
}

// ---------------------------------------------------------------------------
// 2) merged gauss kernel, tiled per 16x16 pixel block: [b][tx][ty][ij][256]
__global__ void k_gauss(const float* __restrict__ pos_sdims,
                        const float* __restrict__ pos_compat,
                        const float* __restrict__ col_compat) {
    __shared__ float cf_s[3][26*26];
    __shared__ float pos_s[KKn];
    int tyi = blockIdx.x, txi = blockIdx.y, b = blockIdx.z;
    int t = threadIdx.x;
    int x0 = txi*16 - SPANn, y0 = tyi*16 - SPANn;
    if (t < KKn) {
        int i = t / 11, j = t - i*11;
        int dx = i - SPANn, dy = j - SPANn;
        float sd4 = 4.f * pos_sdims[0];
        float dpos2 = sd4*sd4 * (float)(dx*dx + dy*dy);
        pos_s[t] = pos_compat[0] * __expf(-0.5f*dpos2);
    }
    for (int i = t; i < 3*676; i += 256) {
        int c = i / 676, rem = i % 676;
        int xx = x0 + rem/26, yy = y0 + rem%26;
        float v = 0.f;
        if ((unsigned)xx < HL && (unsigned)yy < WL)
            v = g_cf[((b*3 + c)*HL + xx)*WL + yy];
        cf_s[c][rem] = v;
    }
    __syncthreads();
    int px = t >> 4, py = t & 15;
    int ctr = (px + SPANn)*26 + (py + SPANn);
    float c0 = cf_s[0][ctr], c1 = cf_s[1][ctr], c2 = cf_s[2][ctr];
    float cc = col_compat[0];
    int gx = txi*16 + px, gy = tyi*16 + py;
    float* outb = g_gk + (size_t)(((b*8 + txi)*8 + tyi)*KKn)*256 + t;
    #pragma unroll 1
    for (int ij = 0; ij < KKn; ij++) {
        int i = ij / 11, j = ij - i*11;
        int dx = i - SPANn, dy = j - SPANn;
        bool valid = ((unsigned)(gx + dx) < HL) && ((unsigned)(gy + dy) < WL);
        int si = (px + i)*26 + (py + j);
        float d0 = cf_s[0][si] - c0;
        float d1 = cf_s[1][si] - c1;
        float d2 = cf_s[2][si] - c2;
        float dcol2 = d0*d0 + d1*d1 + d2*d2;
        float gval = valid ? (pos_s[ij] + cc * __expf(-0.5f*dcol2)) : 0.f;
        outb[ij*256] = gval;
    }
}

// ---------------------------------------------------------------------------
// 3) log_softmax(unary) -> g_lg, pooled init pred -> g_ppad
//    128 threads, tile 16x x 32y, grid (16,32,Bn) = 1024 blocks
__global__ __launch_bounds__(128) void k_init(const float* __restrict__ unary) {
    int b = blockIdx.z;
    int w = threadIdx.x >> 5, l = threadIdx.x & 31;
    int x0 = blockIdx.y*16 + w*4;
    int Y  = blockIdx.x*32 + l;
    const float* up  = unary + ((size_t)(b*Cn)*Hn + x0)*Wn + Y;
    float*       lgp = g_lg  + ((size_t)(b*Cn)*Hn + x0)*Wn + Y;
    float pool[Cn];
    #pragma unroll
    for (int c = 0; c < Cn; c++) pool[c] = 0.f;
    #pragma unroll
    for (int r = 0; r < 4; r++) {
        float u[Cn];
        float m = -1e30f;
        #pragma unroll
        for (int c = 0; c < Cn; c++) {
            u[c] = __ldg(up + (size_t)c*Hn*Wn + r*Wn);
            m = fmaxf(m, u[c]);
        }
        float s = 0.f;
        #pragma unroll
        for (int c = 0; c < Cn; c++) s += __expf(u[c] - m);
        float lse = m + __logf(s);
        #pragma unroll
        for (int c = 0; c < Cn; c++) {
            float v = u[c] - lse;
            lgp[(size_t)c*Hn*Wn + r*Wn] = v;
            pool[c] += v;
        }
    }
    int xp = (x0 >> 2) + XOFF;
    int yp = (Y  >> 2) + YOFF;
    #pragma unroll
    for (int c = 0; c < Cn; c++) {
        float r = pool[c];
        r += __shfl_xor_sync(0xffffffffu, r, 1);
        r += __shfl_xor_sync(0xffffffffu, r, 2);
        if ((l & 3) == 0)
            g_ppad[((size_t)(b*Cn + c)*PP + xp)*PP + yp] = r * 0.0625f;
    }
}

// ---------------------------------------------------------------------------
// 4) message passing, register row-cached stencil.
//    672 threads = 21 warps; warp = one channel; lane = (16 px-rows x 2 cgroups)
__global__ __launch_bounds__(672) void k_msg() {
    __shared__ float gk_s[2][11*GKROW];
    const int t = threadIdx.x;
    const int b = blockIdx.z;
    const int tyi = blockIdx.x, txi = blockIdx.y;
    const int chan = t >> 5, lane = t & 31;
    const int pxrow = lane >> 1, cg = lane & 1;
    const int pxg = txi*16 + pxrow;
    const int Yb  = tyi*16 + cg*8;
    const float* gbase = g_gk + (size_t)(((b*8 + txi)*8 + tyi)*KKn)*256;

    float4 st[2];
    {
        const float4* src = (const float4*)gbase;
        #pragma unroll
        for (int k = 0; k < 2; k++) {
            int idx = t + k*672;
            st[k] = (idx < 704) ? __ldg(src + idx) : make_float4(0.f,0.f,0.f,0.f);
        }
        #pragma unroll
        for (int k = 0; k < 2; k++) {
            int idx = t + k*672;
            if (idx < 704) {
                int j = idx >> 6, pq = idx & 63;
                int pos = j*GKROW + (pq >> 1)*12 + (pq & 1)*4;
                *(float4*)(&gk_s[0][pos]) = st[k];
            }
        }
    }
    __syncthreads();

    float acc[8];
    #pragma unroll
    for (int k = 0; k < 8; k++) acc[k] = 0.f;

    const int gkoff = lane * 12;
    const float* prow_base = g_ppad + ((size_t)(b*Cn + chan)*PP + pxg)*PP + Yb;

    #pragma unroll 1
    for (int i = 0; i < 11; i++) {
        if (i < 10) {
            const float4* src = (const float4*)(gbase + (size_t)(i+1)*11*256);
            #pragma unroll
            for (int k = 0; k < 2; k++) {
                int idx = t + k*672;
                st[k] = (idx < 704) ? __ldg(src + idx) : make_float4(0.f,0.f,0.f,0.f);
            }
        }
        float pr[24];
        {
            const float4* pp = (const float4*)(prow_base + (size_t)i*PP);
            #pragma unroll
            for (int q = 0; q < 6; q++) {
                float4 v = __ldg(pp + q);
                pr[q*4+0] = v.x; pr[q*4+1] = v.y;
                pr[q*4+2] = v.z; pr[q*4+3] = v.w;
            }
        }
        const float* gs = gk_s[i & 1];
        #pragma unroll
        for (int j = 0; j < 11; j++) {
            float4 ga = *(const float4*)(gs + j*GKROW + gkoff);
            float4 gb = *(const float4*)(gs + j*GKROW + gkoff + 4);
            acc[0] += ga.x * pr[0 + j + 3];
            acc[1] += ga.y * pr[1 + j + 3];
            acc[2] += ga.z * pr[2 + j + 3];
            acc[3] += ga.w * pr[3 + j + 3];
            acc[4] += gb.x * pr[4 + j + 3];
            acc[5] += gb.y * pr[5 + j + 3];
            acc[6] += gb.z * pr[6 + j + 3];
            acc[7] += gb.w * pr[7 + j + 3];
        }
        if (i < 10) {
            __syncthreads();
            #pragma unroll
            for (int k = 0; k < 2; k++) {
                int idx = t + k*672;
                if (idx < 704) {
                    int j = idx >> 6, pq = idx & 63;
                    int pos = j*GKROW + (pq >> 1)*12 + (pq & 1)*4;
                    *(float4*)(&gk_s[(i+1) & 1][pos]) = st[k];
                }
            }
            __syncthreads();
        }
    }

    float* mp = g_msg + ((size_t)(b*Cn + chan)*HL + pxg)*WL + Yb;
    *(float4*)mp       = make_float4(acc[0], acc[1], acc[2], acc[3]);
    *(float4*)(mp + 4) = make_float4(acc[4], acc[5], acc[6], acc[7]);
}

// ---------------------------------------------------------------------------
// 5) fused: bilinear-up(msg) blend, softmax, pool -> g_ppad
//    128 threads, tile 16x x 32y, grid (16,32,Bn)
__global__ __launch_bounds__(128) void k_iter(const float* __restrict__ weight) {
    __shared__ float m_s[Cn*60];   // [c][6][10]
    int b = blockIdx.z;
    int t = threadIdx.x, w = t >> 5, l = t & 31;
    int lx0 = blockIdx.y*4 - 1, ly0 = blockIdx.x*8 - 1;
    for (int i = t; i < Cn*60; i += 128) {
        int c = i / 60, rem = i % 60;
        int xx = lx0 + rem/10; xx = max(0, min(HL-1, xx));
        int yy = ly0 + rem%10; yy = max(0, min(WL-1, yy));
        m_s[i] = g_msg[((b*Cn + c)*HL + xx)*WL + yy];
    }
    __syncthreads();
    int x0 = blockIdx.y*16 + w*4;
    int Y  = blockIdx.x*32 + l;
    const float* lgp = g_lg + ((size_t)(b*Cn)*Hn + x0)*Wn + Y;
    float wgt = weight[0], uw = 1.f - wgt;
    int ry = l & 3;
    float wy0 = c_wtab[ry], wy1 = 1.f - wy0;
    int yA = (l >> 2) + 1 + ((ry < 2) ? -1 : 0);
    float pool[Cn];
    #pragma unroll
    for (int c = 0; c < Cn; c++) pool[c] = 0.f;
    #pragma unroll
    for (int r = 0; r < 4; r++) {
        float wx0 = c_wtab[r], wx1 = 1.f - wx0;
        int xA = w + 1 + ((r < 2) ? -1 : 0);
        int base = xA*10 + yA;
        float v[Cn];
        float mmax = -1e30f;
        #pragma unroll
        for (int c = 0; c < Cn; c++) {
            const float* mc = m_s + c*60 + base;
            float mu = wx0*(wy0*mc[0] + wy1*mc[1]) + wx1*(wy0*mc[10] + wy1*mc[11]);
            float vv = uw * __ldg(lgp + (size_t)c*Hn*Wn + r*Wn) + wgt * mu;
            v[c] = vv;
            mmax = fmaxf(mmax, vv);
        }
        float s = 0.f;
        #pragma unroll
        for (int c = 0; c < Cn; c++) { v[c] = __expf(v[c] - mmax); s += v[c]; }
        float inv = 1.f / s;
        #pragma unroll
        for (int c = 0; c < Cn; c++) pool[c] += v[c] * inv;
    }
    int xp = (x0 >> 2) + XOFF;
    int yp = (Y  >> 2) + YOFF;
    #pragma unroll
    for (int c = 0; c < Cn; c++) {
        float r = pool[c];
        r += __shfl_xor_sync(0xffffffffu, r, 1);
        r += __shfl_xor_sync(0xffffffffu, r, 2);
        if ((l & 3) == 0)
            g_ppad[((size_t)(b*Cn + c)*PP + xp)*PP + yp] = r * 0.0625f;
    }
}

// ---------------------------------------------------------------------------
// 6) final: write full-res pred (no softmax/pool)
__global__ __launch_bounds__(128) void k_final(const float* __restrict__ weight, float* __restrict__ out) {
    __shared__ float m_s[Cn*60];
    int b = blockIdx.z;
    int t = threadIdx.x, w = t >> 5, l = t & 31;
    int lx0 = blockIdx.y*4 - 1, ly0 = blockIdx.x*8 - 1;
    for (int i = t; i < Cn*60; i += 128) {
        int c = i / 60, rem = i % 60;
        int xx = lx0 + rem/10; xx = max(0, min(HL-1, xx));
        int yy = ly0 + rem%10; yy = max(0, min(WL-1, yy));
        m_s[i] = g_msg[((b*Cn + c)*HL + xx)*WL + yy];
    }
    __syncthreads();
    int x0 = blockIdx.y*16 + w*4;
    int Y  = blockIdx.x*32 + l;
    const float* lgp  = g_lg + ((size_t)(b*Cn)*Hn + x0)*Wn + Y;
    float*       outp = out  + ((size_t)(b*Cn)*Hn + x0)*Wn + Y;
    float wgt = weight[0], uw = 1.f - wgt;
    int ry = l & 3;
    float wy0 = c_wtab[ry], wy1 = 1.f - wy0;
    int yA = (l >> 2) + 1 + ((ry < 2) ? -1 : 0);
    #pragma unroll
    for (int r = 0; r < 4; r++) {
        float wx0 = c_wtab[r], wx1 = 1.f - wx0;
        int xA = w + 1 + ((r < 2) ? -1 : 0);
        int base = xA*10 + yA;
        #pragma unroll
        for (int c = 0; c < Cn; c++) {
            const float* mc = m_s + c*60 + base;
            float mu = wx0*(wy0*mc[0] + wy1*mc[1]) + wx1*(wy0*mc[10] + wy1*mc[11]);
            outp[(size_t)c*Hn*Wn + r*Wn] =
                uw * __ldg(lgp + (size_t)c*Hn*Wn + r*Wn) + wgt * mu;
        }
    }
}

// ---------------------------------------------------------------------------
extern "C" void kernel_launch(void* const* d_in, const int* in_sizes, int n_in,
                              void* d_out, int out_size) {
    const float* unary      = (const float*)d_in[0];
    const float* img        = (const float*)d_in[1];
    const float* pos_sdims  = (const float*)d_in[2];
    const float* col_schan  = (const float*)d_in[3];
    const float* pos_compat = (const float*)d_in[4];
    const float* col_compat = (const float*)d_in[5];
    const float* weight     = (const float*)d_in[6];
    float* out = (float*)d_out;

    k_zero<<<(Bn*Cn*PLANE/4 + 255)/256, 256>>>();
    k_pool_img<<<(Bn*3*HL*WL + 255)/256, 256>>>(img, col_schan);
    k_gauss<<<dim3(8, 8, Bn), 256>>>(pos_sdims, pos_compat, col_compat);
    k_init<<<dim3(16, 32, Bn), 128>>>(unary);
    for (int it = 0; it < 5; it++) {
        k_msg<<<dim3(8, 8, Bn), 672>>>();
        if (it < 4)
            k_iter<<<dim3(16, 32, Bn), 128>>>(weight);
        else
            k_final<<<dim3(16, 32, Bn), 128>>>(weight, out);
    }
}